// round 13
// baseline (speedup 1.0000x reference)
#include <cuda_runtime.h>
#include <cuda_fp16.h>
#include <cstdint>

#define ROWS_REAL 9800          // 2 * 70 * 70 padded-grid rows
#define ROWS_PAD  9856          // 616 * 16
#define NOUT      768           // q | kf | vf packed
#define NR16      616           // ROWS_PAD / 16
#define NK16A     32            // A K16 steps: [hi(256) | lo(256)]
#define NK16B     16            // B K16 steps: hi only (reused for both halves)
#define NN8       96            // NOUT / 8

// Fragment-linear operand storage (fp16 split-2):
//   A2f: [R16 frag][K16 0..31][lane][8 halfs]  (a0|a1|a2|a3 pairs); K16>=16 = lo seg
//   B2f: [N8 frag][K16 0..15][lane][4 halfs]   (b0|b1 pairs); hi only
__device__ __half g_A2f[NR16 * NK16A * 32 * 8];
__device__ __half g_B2f[NN8 * NK16B * 32 * 4];
__device__ float g_C[ROWS_PAD * NOUT];          // [q | kf | vf]
__device__ float g_bwin[49 * 256];              // transposed bias window [j][c]

// ---------------- helpers ----------------
__device__ __forceinline__ int reflect64(int i) {
    if (i < 0) i = -i - 1;
    if (i > 63) i = 127 - i;
    return i;
}
__device__ __forceinline__ float ex2f(float x) {
    float r;
    asm("ex2.approx.ftz.f32 %0, %1;" : "=f"(r) : "f"(x));
    return r;
}
__device__ __forceinline__ void mma16816(float* c, const uint32_t* a, uint32_t b0, uint32_t b1) {
    asm volatile(
        "mma.sync.aligned.m16n8k16.row.col.f32.f16.f16.f32 "
        "{%0,%1,%2,%3}, {%4,%5,%6,%7}, {%8,%9}, {%0,%1,%2,%3};"
        : "+f"(c[0]), "+f"(c[1]), "+f"(c[2]), "+f"(c[3])
        : "r"(a[0]), "r"(a[1]), "r"(a[2]), "r"(a[3]), "r"(b0), "r"(b1));
}
__device__ __forceinline__ __half hf_hi(float v) { return __float2half_rn(v); }
__device__ __forceinline__ __half hf_lo(float v) {
    __half h = __float2half_rn(v);
    return __float2half_rn(v - __half2float(h));
}

// ---------------- prep: A fragments (symmetric-padded x, fp16 [hi|lo]) ----------------
__global__ void prep_a2f_kernel(const float* __restrict__ x) {
    int tid = blockIdx.x * blockDim.x + threadIdx.x;
    if (tid >= NR16 * NK16A * 32) return;
    int lane = tid & 31;
    int f = tid >> 5;
    int K16 = f % NK16A;
    int R16 = f / NK16A;
    bool lo = (K16 >= 16);
    int kc  = (K16 & 15) * 16 + (lane & 3) * 2;

    int re = R16 * 16 + (lane >> 2);
    int ro = re + 8;

    const float* pe = nullptr;
    const float* po = nullptr;
    if (re < ROWS_REAL) {
        int b = re / 4900, rem = re - b * 4900;
        int hp = rem / 70, wp = rem - hp * 70;
        pe = x + ((((b << 6) + reflect64(hp - 3)) << 6) + reflect64(wp - 3)) * 256;
    }
    if (ro < ROWS_REAL) {
        int b = ro / 4900, rem = ro - b * 4900;
        int hp = rem / 70, wp = rem - hp * 70;
        po = x + ((((b << 6) + reflect64(hp - 3)) << 6) + reflect64(wp - 3)) * 256;
    }

    __half o[8];
#pragma unroll
    for (int h = 0; h < 2; h++) {
        float ve0 = pe ? pe[kc + h]     : 0.f;
        float vo0 = po ? po[kc + h]     : 0.f;
        float ve8 = pe ? pe[kc + 8 + h] : 0.f;
        float vo8 = po ? po[kc + 8 + h] : 0.f;
        o[0 + h] = lo ? hf_lo(ve0) : hf_hi(ve0);   // a0
        o[2 + h] = lo ? hf_lo(vo0) : hf_hi(vo0);   // a1
        o[4 + h] = lo ? hf_lo(ve8) : hf_hi(ve8);   // a2
        o[6 + h] = lo ? hf_lo(vo8) : hf_hi(vo8);   // a3
    }
    *(uint4*)(g_A2f + (size_t)tid * 8) = *(uint4*)o;
}

// ---------------- prep: B fragments (wcat^T, fp16 hi only) ----------------
__global__ void prep_b2f_kernel(const float* __restrict__ wq,
                                const float* __restrict__ wk,
                                const float* __restrict__ wv) {
    int tid = blockIdx.x * blockDim.x + threadIdx.x;
    if (tid >= NN8 * NK16B * 32) return;
    int lane = tid & 31;
    int f = tid >> 5;
    int K16 = f % NK16B;
    int N8  = f / NK16B;
    int kc  = K16 * 16 + (lane & 3) * 2;

    int n = N8 * 8 + (lane >> 2);
    int sel = n >> 8, cc = n & 255;
    const float* w = (sel == 0) ? wq : (sel == 1 ? wk : wv);

    __half o[4];
#pragma unroll
    for (int h = 0; h < 2; h++) {
        o[0 + h] = hf_hi(w[(kc + h) * 256 + cc]);      // b0
        o[2 + h] = hf_hi(w[(kc + 8 + h) * 256 + cc]);  // b1
    }
    *(uint2*)(g_B2f + (size_t)tid * 4) = *(uint2*)o;
}

// ---------------- prep: transposed bias window table Bwin[j][c] ----------------
__global__ void prep_bwin_kernel(const float* __restrict__ rh,
                                 const float* __restrict__ rw) {
    int idx = blockIdx.x * blockDim.x + threadIdx.x;
    if (idx >= 49 * 256) return;
    int j = idx >> 8;
    int c = idx & 255;
    int u = c * 49 + j;
    int ch = u & 255;
    int tap = u >> 8;
    int kh = (tap * 37) >> 8;
    int kw = tap - kh * 7;
    g_bwin[idx] = (ch < 128) ? rh[kh * 128 + ch] : rw[kw * 128 + (ch - 128)];
}

// ---------------- smem-free mma.sync GEMM (fp16 split-2, depth-3 prefetch) ----------------
// BM=128 BN=128, 8 warps (2x4), warp tile 64x32, 1 CTA/SM, 4-buffer rotation.
__global__ __launch_bounds__(256, 1) void mma_gemm_kernel() {
    int tid = threadIdx.x;
    int lane = tid & 31, wid = tid >> 5;
    int wm = wid >> 2, wn = wid & 3;
    int fragR0 = blockIdx.y * 8  + wm * 4;    // R16 frag base
    int fragN0 = blockIdx.x * 16 + wn * 4;    // N8 frag base

    const uint4* Af = (const uint4*)g_A2f;
    const uint2* Bf = (const uint2*)g_B2f;

    const uint4* pA[4];
    const uint2* pB[4];
#pragma unroll
    for (int mt = 0; mt < 4; mt++) pA[mt] = Af + ((size_t)(fragR0 + mt) * NK16A) * 32 + lane;
#pragma unroll
    for (int nt = 0; nt < 4; nt++) pB[nt] = Bf + ((size_t)(fragN0 + nt) * NK16B) * 32 + lane;

    float acc[4][4][4];
#pragma unroll
    for (int i = 0; i < 4; i++)
#pragma unroll
        for (int j = 0; j < 4; j++)
#pragma unroll
            for (int v = 0; v < 4; v++) acc[i][j][v] = 0.f;

    uint4 a[4][4];   // [buf][mt]
    uint2 b[4][4];   // [buf][nt]
#pragma unroll
    for (int s = 0; s < 3; s++) {
#pragma unroll
        for (int mt = 0; mt < 4; mt++) a[s][mt] = pA[mt][s * 32];
#pragma unroll
        for (int nt = 0; nt < 4; nt++) b[s][nt] = pB[nt][s * 32];   // s < 16
    }

#pragma unroll 4
    for (int kt = 0; kt < NK16A; kt++) {
        int pf = kt + 3;
        if (pf < NK16A) {
#pragma unroll
            for (int mt = 0; mt < 4; mt++) a[pf & 3][mt] = pA[mt][pf * 32];
#pragma unroll
            for (int nt = 0; nt < 4; nt++) b[pf & 3][nt] = pB[nt][(pf & 15) * 32];
        }
#pragma unroll
        for (int mt = 0; mt < 4; mt++)
#pragma unroll
            for (int nt = 0; nt < 4; nt++)
                mma16816(acc[mt][nt], (const uint32_t*)&a[kt & 3][mt],
                         b[kt & 3][nt].x, b[kt & 3][nt].y);
    }

    // epilogue: m16n8 fragments -> g_C
    int row0 = blockIdx.y * 128, col0 = blockIdx.x * 128;
    int qr = lane >> 2;
    int qc = (lane & 3) * 2;
#pragma unroll
    for (int mt = 0; mt < 4; mt++) {
#pragma unroll
        for (int nt = 0; nt < 4; nt++) {
            int rr = row0 + wm * 64 + mt * 16 + qr;
            int cc = col0 + wn * 32 + nt * 8 + qc;
            *(float2*)(g_C + (size_t)rr * 768 + cc)       = make_float2(acc[mt][nt][0], acc[mt][nt][1]);
            *(float2*)(g_C + (size_t)(rr + 8) * 768 + cc) = make_float2(acc[mt][nt][2], acc[mt][nt][3]);
        }
    }
}

// ---------------- attention: 4x4 spatial tile (proven R9-R11 config) ----------------
// 10x10 window rows shared by 16 positions: 100 rows x [K 256f | V 256f] = 200 KB smem.
__global__ __launch_bounds__(512, 1) void attn_kernel(float* __restrict__ out) {
    extern __shared__ float sm[];          // 100 * 512 floats

    int t = threadIdx.x;
    int bid = blockIdx.x;
    int w4 = bid & 15, h4 = (bid >> 4) & 15, b = bid >> 8;
    int h0 = h4 * 4, w0 = w4 * 4;

    const float4* C4 = (const float4*)g_C;
    float4* sm4 = (float4*)sm;

    // stage K+V: 100 rows x 128 float4s = 12800 float4s, 25 per thread
#pragma unroll
    for (int i = 0; i < 25; i++) {
        int idx = i * 512 + t;
        int r = idx >> 7;                  // window row 0..99
        int which = (idx >> 6) & 1;        // 0=K, 1=V
        int ch4 = idx & 63;
        int rr10 = (r * 205) >> 11;        // r / 10 (exact for r < 103)
        int rc = r - rr10 * 10;
        int grow = (b * 70 + h0 + rr10) * 70 + (w0 + rc);
        sm4[r * 128 + (which << 6) + ch4] = C4[grow * 192 + 64 + (which << 6) + ch4];
    }
    __syncthreads();

    int slot = t >> 8;
    int c = t & 255;
    int u0 = c * 49;
    int tap0 = u0 >> 8;
    int ch0 = u0 & 255;
    int kh0 = (tap0 * 37) >> 8;
    int kw0 = tap0 - kh0 * 7;
    int n1 = 256 - ch0; if (n1 > 49) n1 = 49;
    int kh1 = kh0, kw1 = kw0 + 1;
    if (kw1 == 7) { kw1 = 0; kh1++; }

    float breg[49];
#pragma unroll
    for (int j = 0; j < 49; j++)
        breg[j] = __ldg(&g_bwin[j * 256 + c]);

#pragma unroll 1
    for (int p = 0; p < 8; p++) {
        int posid = slot * 8 + p;
        int dh = posid >> 2, dw = posid & 3;
        float q = g_C[((b * 70 + h0 + dh + 3) * 70 + (w0 + dw + 3)) * 768 + c];
        float ql2 = q * 1.4426950408889634f;

        int baseA = ((dh + kh0) * 10 + dw + kw0) * 512 + ch0;
        int baseB = ((dh + kh1) * 10 + dw + kw1) * 512 - n1;

        float s0 = 0.f, s1 = 0.f, a0 = 0.f, a1 = 0.f;
#pragma unroll
        for (int j = 0; j < 49; j++) {
            int a = (j < n1) ? baseA : baseB;
            float kv = sm[a + j];
            float vv = sm[a + j + 256];
            float e = ex2f(ql2 * kv);
            if (j & 1) { s1 += e; a1 += e * (vv + breg[j]); }
            else       { s0 += e; a0 += e * (vv + breg[j]); }
        }
        out[((b * 64 + h0 + dh) * 64 + (w0 + dw)) * 256 + c] = (a0 + a1) / (s0 + s1);
    }
}

// ---------------- launch ----------------
extern "C" void kernel_launch(void* const* d_in, const int* in_sizes, int n_in,
                              void* d_out, int out_size) {
    const float* x  = (const float*)d_in[0];
    const float* wq = (const float*)d_in[1];
    const float* wk = (const float*)d_in[2];
    const float* wv = (const float*)d_in[3];
    const float* rh = (const float*)d_in[4];
    const float* rw = (const float*)d_in[5];
    float* out = (float*)d_out;

    prep_a2f_kernel<<<(NR16 * NK16A * 32 + 255) / 256, 256>>>(x);
    prep_b2f_kernel<<<(NN8 * NK16B * 32 + 255) / 256, 256>>>(wq, wk, wv);
    prep_bwin_kernel<<<49, 256>>>(rh, rw);

    dim3 ggrid(6, 77);   // N-tiles x M-tiles (BM=128)
    mma_gemm_kernel<<<ggrid, 256>>>();

    cudaFuncSetAttribute(attn_kernel,
                         cudaFuncAttributeMaxDynamicSharedMemorySize, 204800);
    attn_kernel<<<512, 512, 204800>>>(out);
}

// round 15
// speedup vs baseline: 1.0207x; 1.0207x over previous
#include <cuda_runtime.h>
#include <cuda_fp16.h>
#include <cstdint>

#define ROWS_REAL 9800          // 2 * 70 * 70 padded-grid rows
#define ROWS_PAD  9856          // 616 * 16
#define NOUT      768           // q | kf | vf packed
#define NR16      616           // ROWS_PAD / 16
#define NK16A     32            // A K16 steps: [hi(256) | lo(256)]
#define NK16B     16            // B K16 steps: hi only (reused for both halves)
#define NN8       96            // NOUT / 8

// Fragment-linear operand storage (fp16 split-2):
//   A2f: [R16 frag][K16 0..31][lane][8 halfs]  (a0|a1|a2|a3 pairs); K16>=16 = lo seg
//   B2f: [N8 frag][K16 0..15][lane][4 halfs]   (b0|b1 pairs); hi only
__device__ __half g_A2f[NR16 * NK16A * 32 * 8];
__device__ __half g_B2f[NN8 * NK16B * 32 * 4];
__device__ float g_C[ROWS_PAD * NOUT];          // [q | kf | vf]
__device__ float g_bwin[49 * 256];              // transposed bias window [j][c]

#define A2F_BLOCKS 2464         // 630784 threads / 256
#define B2F_BLOCKS 192          // 49152 / 256
#define BWIN_BLOCKS 49          // 12544 / 256

// ---------------- helpers ----------------
__device__ __forceinline__ int reflect64(int i) {
    if (i < 0) i = -i - 1;
    if (i > 63) i = 127 - i;
    return i;
}
__device__ __forceinline__ float ex2f(float x) {
    float r;
    asm("ex2.approx.ftz.f32 %0, %1;" : "=f"(r) : "f"(x));
    return r;
}
__device__ __forceinline__ void mma16816(float* c, const uint32_t* a, uint32_t b0, uint32_t b1) {
    asm volatile(
        "mma.sync.aligned.m16n8k16.row.col.f32.f16.f16.f32 "
        "{%0,%1,%2,%3}, {%4,%5,%6,%7}, {%8,%9}, {%0,%1,%2,%3};"
        : "+f"(c[0]), "+f"(c[1]), "+f"(c[2]), "+f"(c[3])
        : "r"(a[0]), "r"(a[1]), "r"(a[2]), "r"(a[3]), "r"(b0), "r"(b1));
}
__device__ __forceinline__ __half hf_hi(float v) { return __float2half_rn(v); }
__device__ __forceinline__ __half hf_lo(float v) {
    __half h = __float2half_rn(v);
    return __float2half_rn(v - __half2float(h));
}

// ---------------- fused prep: A2f | B2f | bwin in one launch ----------------
__global__ __launch_bounds__(256) void prep_fused_kernel(
        const float* __restrict__ x,
        const float* __restrict__ wq,
        const float* __restrict__ wk,
        const float* __restrict__ wv,
        const float* __restrict__ rh,
        const float* __restrict__ rw) {
    int blk = blockIdx.x;

    if (blk < A2F_BLOCKS) {
        // ---- A fragments (symmetric-padded x, fp16 [hi|lo]) ----
        int tid = blk * 256 + threadIdx.x;
        if (tid >= NR16 * NK16A * 32) return;
        int lane = tid & 31;
        int f = tid >> 5;
        int K16 = f % NK16A;
        int R16 = f / NK16A;
        bool lo = (K16 >= 16);
        int kc  = (K16 & 15) * 16 + (lane & 3) * 2;

        int re = R16 * 16 + (lane >> 2);
        int ro = re + 8;

        const float* pe = nullptr;
        const float* po = nullptr;
        if (re < ROWS_REAL) {
            int b = re / 4900, rem = re - b * 4900;
            int hp = rem / 70, wp = rem - hp * 70;
            pe = x + ((((b << 6) + reflect64(hp - 3)) << 6) + reflect64(wp - 3)) * 256;
        }
        if (ro < ROWS_REAL) {
            int b = ro / 4900, rem = ro - b * 4900;
            int hp = rem / 70, wp = rem - hp * 70;
            po = x + ((((b << 6) + reflect64(hp - 3)) << 6) + reflect64(wp - 3)) * 256;
        }

        __half o[8];
#pragma unroll
        for (int h = 0; h < 2; h++) {
            float ve0 = pe ? pe[kc + h]     : 0.f;
            float vo0 = po ? po[kc + h]     : 0.f;
            float ve8 = pe ? pe[kc + 8 + h] : 0.f;
            float vo8 = po ? po[kc + 8 + h] : 0.f;
            o[0 + h] = lo ? hf_lo(ve0) : hf_hi(ve0);   // a0
            o[2 + h] = lo ? hf_lo(vo0) : hf_hi(vo0);   // a1
            o[4 + h] = lo ? hf_lo(ve8) : hf_hi(ve8);   // a2
            o[6 + h] = lo ? hf_lo(vo8) : hf_hi(vo8);   // a3
        }
        *(uint4*)(g_A2f + (size_t)tid * 8) = *(uint4*)o;

    } else if (blk < A2F_BLOCKS + B2F_BLOCKS) {
        // ---- B fragments (wcat^T, fp16 hi only) ----
        int tid = (blk - A2F_BLOCKS) * 256 + threadIdx.x;
        if (tid >= NN8 * NK16B * 32) return;
        int lane = tid & 31;
        int f = tid >> 5;
        int K16 = f % NK16B;
        int N8  = f / NK16B;
        int kc  = K16 * 16 + (lane & 3) * 2;

        int n = N8 * 8 + (lane >> 2);
        int sel = n >> 8, cc = n & 255;
        const float* w = (sel == 0) ? wq : (sel == 1 ? wk : wv);

        __half o[4];
#pragma unroll
        for (int h = 0; h < 2; h++) {
            o[0 + h] = hf_hi(w[(kc + h) * 256 + cc]);      // b0
            o[2 + h] = hf_hi(w[(kc + 8 + h) * 256 + cc]);  // b1
        }
        *(uint2*)(g_B2f + (size_t)tid * 4) = *(uint2*)o;

    } else {
        // ---- transposed bias window table Bwin[j][c] ----
        int idx = (blk - A2F_BLOCKS - B2F_BLOCKS) * 256 + threadIdx.x;
        if (idx >= 49 * 256) return;
        int j = idx >> 8;
        int c = idx & 255;
        int u = c * 49 + j;
        int ch = u & 255;
        int tap = u >> 8;
        int kh = (tap * 37) >> 8;
        int kw = tap - kh * 7;
        g_bwin[idx] = (ch < 128) ? rh[kh * 128 + ch] : rw[kw * 128 + (ch - 128)];
    }
}

// ---------------- smem-free mma.sync GEMM (R11 exact): C = A2 . B2^T ----------------
// BM=128 BN=128, 8 warps (2x4), warp tile 64x32, depth-1 double-buffer, 2 CTA/SM.
__global__ __launch_bounds__(256, 2) void mma_gemm_kernel() {
    int tid = threadIdx.x;
    int lane = tid & 31, wid = tid >> 5;
    int wm = wid >> 2, wn = wid & 3;
    int fragR0 = blockIdx.y * 8  + wm * 4;    // R16 frag base
    int fragN0 = blockIdx.x * 16 + wn * 4;    // N8 frag base

    const uint4* Af = (const uint4*)g_A2f;
    const uint2* Bf = (const uint2*)g_B2f;

    const uint4* pA[4];
    const uint2* pB[4];
#pragma unroll
    for (int mt = 0; mt < 4; mt++) pA[mt] = Af + ((size_t)(fragR0 + mt) * NK16A) * 32 + lane;
#pragma unroll
    for (int nt = 0; nt < 4; nt++) pB[nt] = Bf + ((size_t)(fragN0 + nt) * NK16B) * 32 + lane;

    float acc[4][4][4];
#pragma unroll
    for (int i = 0; i < 4; i++)
#pragma unroll
        for (int j = 0; j < 4; j++)
#pragma unroll
            for (int v = 0; v < 4; v++) acc[i][j][v] = 0.f;

    uint4 a[4]; uint2 b[4];
    uint4 an[4]; uint2 bn[4];
#pragma unroll
    for (int mt = 0; mt < 4; mt++) a[mt] = pA[mt][0];
#pragma unroll
    for (int nt = 0; nt < 4; nt++) b[nt] = pB[nt][0];

#pragma unroll 4
    for (int kt = 0; kt < NK16A; kt += 2) {
#pragma unroll
        for (int mt = 0; mt < 4; mt++) an[mt] = pA[mt][(kt + 1) * 32];
#pragma unroll
        for (int nt = 0; nt < 4; nt++) bn[nt] = pB[nt][((kt + 1) & 15) * 32];
#pragma unroll
        for (int mt = 0; mt < 4; mt++)
#pragma unroll
            for (int nt = 0; nt < 4; nt++)
                mma16816(acc[mt][nt], (const uint32_t*)&a[mt], b[nt].x, b[nt].y);
        if (kt + 2 < NK16A) {
#pragma unroll
            for (int mt = 0; mt < 4; mt++) a[mt] = pA[mt][(kt + 2) * 32];
#pragma unroll
            for (int nt = 0; nt < 4; nt++) b[nt] = pB[nt][((kt + 2) & 15) * 32];
        }
#pragma unroll
        for (int mt = 0; mt < 4; mt++)
#pragma unroll
            for (int nt = 0; nt < 4; nt++)
                mma16816(acc[mt][nt], (const uint32_t*)&an[mt], bn[nt].x, bn[nt].y);
    }

    // epilogue: m16n8 fragments -> g_C
    int row0 = blockIdx.y * 128, col0 = blockIdx.x * 128;
    int qr = lane >> 2;
    int qc = (lane & 3) * 2;
#pragma unroll
    for (int mt = 0; mt < 4; mt++) {
#pragma unroll
        for (int nt = 0; nt < 4; nt++) {
            int rr = row0 + wm * 64 + mt * 16 + qr;
            int cc = col0 + wn * 32 + nt * 8 + qc;
            *(float2*)(g_C + (size_t)rr * 768 + cc)       = make_float2(acc[mt][nt][0], acc[mt][nt][1]);
            *(float2*)(g_C + (size_t)(rr + 8) * 768 + cc) = make_float2(acc[mt][nt][2], acc[mt][nt][3]);
        }
    }
}

// ---------------- attention: 4x4 spatial tile (R9-R11 config) + fast divide ----------------
// 10x10 window rows shared by 16 positions: 100 rows x [K 256f | V 256f] = 200 KB smem.
__global__ __launch_bounds__(512, 1) void attn_kernel(float* __restrict__ out) {
    extern __shared__ float sm[];          // 100 * 512 floats

    int t = threadIdx.x;
    int bid = blockIdx.x;
    int w4 = bid & 15, h4 = (bid >> 4) & 15, b = bid >> 8;
    int h0 = h4 * 4, w0 = w4 * 4;

    const float4* C4 = (const float4*)g_C;
    float4* sm4 = (float4*)sm;

    // stage K+V: 100 rows x 128 float4s = 12800 float4s, 25 per thread
#pragma unroll
    for (int i = 0; i < 25; i++) {
        int idx = i * 512 + t;
        int r = idx >> 7;                  // window row 0..99
        int which = (idx >> 6) & 1;        // 0=K, 1=V
        int ch4 = idx & 63;
        int rr10 = (r * 205) >> 11;        // r / 10 (exact for r < 103)
        int rc = r - rr10 * 10;
        int grow = (b * 70 + h0 + rr10) * 70 + (w0 + rc);
        sm4[r * 128 + (which << 6) + ch4] = C4[grow * 192 + 64 + (which << 6) + ch4];
    }
    __syncthreads();

    int slot = t >> 8;
    int c = t & 255;
    int u0 = c * 49;
    int tap0 = u0 >> 8;
    int ch0 = u0 & 255;
    int kh0 = (tap0 * 37) >> 8;
    int kw0 = tap0 - kh0 * 7;
    int n1 = 256 - ch0; if (n1 > 49) n1 = 49;
    int kh1 = kh0, kw1 = kw0 + 1;
    if (kw1 == 7) { kw1 = 0; kh1++; }

    float breg[49];
#pragma unroll
    for (int j = 0; j < 49; j++)
        breg[j] = __ldg(&g_bwin[j * 256 + c]);

#pragma unroll 1
    for (int p = 0; p < 8; p++) {
        int posid = slot * 8 + p;
        int dh = posid >> 2, dw = posid & 3;
        float q = g_C[((b * 70 + h0 + dh + 3) * 70 + (w0 + dw + 3)) * 768 + c];
        float ql2 = q * 1.4426950408889634f;

        int baseA = ((dh + kh0) * 10 + dw + kw0) * 512 + ch0;
        int baseB = ((dh + kh1) * 10 + dw + kw1) * 512 - n1;

        float s0 = 0.f, s1 = 0.f, a0 = 0.f, a1 = 0.f;
#pragma unroll
        for (int j = 0; j < 49; j++) {
            int a = (j < n1) ? baseA : baseB;
            float kv = sm[a + j];
            float vv = sm[a + j + 256];
            float e = ex2f(ql2 * kv);
            if (j & 1) { s1 += e; a1 += e * (vv + breg[j]); }
            else       { s0 += e; a0 += e * (vv + breg[j]); }
        }
        out[((b * 64 + h0 + dh) * 64 + (w0 + dw)) * 256 + c] =
            __fdividef(a0 + a1, s0 + s1);
    }
}

// ---------------- launch ----------------
extern "C" void kernel_launch(void* const* d_in, const int* in_sizes, int n_in,
                              void* d_out, int out_size) {
    const float* x  = (const float*)d_in[0];
    const float* wq = (const float*)d_in[1];
    const float* wk = (const float*)d_in[2];
    const float* wv = (const float*)d_in[3];
    const float* rh = (const float*)d_in[4];
    const float* rw = (const float*)d_in[5];
    float* out = (float*)d_out;

    prep_fused_kernel<<<A2F_BLOCKS + B2F_BLOCKS + BWIN_BLOCKS, 256>>>(
        x, wq, wk, wv, rh, rw);

    dim3 ggrid(6, 77);   // N-tiles x M-tiles (BM=128)
    mma_gemm_kernel<<<ggrid, 256>>>();

    cudaFuncSetAttribute(attn_kernel,
                         cudaFuncAttributeMaxDynamicSharedMemorySize, 204800);
    attn_kernel<<<512, 512, 204800>>>(out);
}